// round 1
// baseline (speedup 1.0000x reference)
#include <cuda_runtime.h>
#include <math.h>

#define NROWS 32768
#define DIM 1024
#define NRES 21

// Scratch (no cudaMalloc allowed): act + h ping-pong, angle buffer.
__device__ float g_act[(size_t)NROWS * DIM];
__device__ float g_h[(size_t)NROWS * DIM];
__device__ float g_ang[(size_t)NROWS * 14];

#define BM 128
#define BN 128
#define BK 8
#define TM 8
#define TN 8

// C[NROWS,DIM] = relu(A0)(+relu(A1)) @ B + bias_scale*bias (+ C if RESID)
template<int DUAL, int RESID>
__global__ __launch_bounds__(256) void gemm_relu(
    const float* __restrict__ A0, const float* __restrict__ A1,
    const float* __restrict__ B, const float* __restrict__ bias,
    float bias_scale, float* __restrict__ C)
{
    __shared__ float As[BK][BM];
    __shared__ float Bs[BK][BN];
    const int tid = threadIdx.x;
    const int bx = blockIdx.x, by = blockIdx.y;
    const int rowA = tid >> 1, colA = (tid & 1) * 4;
    const int rowB = tid >> 5, colB = (tid & 31) * 4;
    const int ty = tid >> 4, tx = tid & 15;

    const float* a0 = A0 + (size_t)(by * BM + rowA) * DIM + colA;
    const float* a1 = A1 + (size_t)(by * BM + rowA) * DIM + colA;
    const float* bp = B + (size_t)rowB * DIM + bx * BN + colB;

    float acc[TM][TN] = {};

    for (int k0 = 0; k0 < DIM; k0 += BK) {
        float4 av = *(const float4*)a0;
        float4 v;
        v.x = fmaxf(av.x, 0.f); v.y = fmaxf(av.y, 0.f);
        v.z = fmaxf(av.z, 0.f); v.w = fmaxf(av.w, 0.f);
        if (DUAL) {
            float4 aw = *(const float4*)a1;
            v.x += fmaxf(aw.x, 0.f); v.y += fmaxf(aw.y, 0.f);
            v.z += fmaxf(aw.z, 0.f); v.w += fmaxf(aw.w, 0.f);
        }
        As[colA + 0][rowA] = v.x;
        As[colA + 1][rowA] = v.y;
        As[colA + 2][rowA] = v.z;
        As[colA + 3][rowA] = v.w;
        *(float4*)&Bs[rowB][colB] = *(const float4*)bp;
        __syncthreads();

        #pragma unroll
        for (int k = 0; k < BK; k++) {
            float rm[TM], rn[TN];
            #pragma unroll
            for (int i = 0; i < TM; i++) rm[i] = As[k][ty * TM + i];
            #pragma unroll
            for (int j = 0; j < TN; j++) rn[j] = Bs[k][tx * TN + j];
            #pragma unroll
            for (int i = 0; i < TM; i++)
                #pragma unroll
                for (int j = 0; j < TN; j++)
                    acc[i][j] = fmaf(rm[i], rn[j], acc[i][j]);
        }
        __syncthreads();
        a0 += BK; a1 += BK; bp += (size_t)BK * DIM;
    }

    const int col0 = bx * BN + tx * TN;
    float bb[TN];
    #pragma unroll
    for (int j = 0; j < TN; j++) bb[j] = bias_scale * bias[col0 + j];

    #pragma unroll
    for (int i = 0; i < TM; i++) {
        float* cp = C + (size_t)(by * BM + ty * TM + i) * DIM + col0;
        #pragma unroll
        for (int j = 0; j < TN; j += 4) {
            float4 r;
            r.x = acc[i][j + 0] + bb[j + 0];
            r.y = acc[i][j + 1] + bb[j + 1];
            r.z = acc[i][j + 2] + bb[j + 2];
            r.w = acc[i][j + 3] + bb[j + 3];
            if (RESID) {
                float4 old = *(const float4*)(cp + j);
                r.x += old.x; r.y += old.y; r.z += old.z; r.w += old.w;
            }
            *(float4*)(cp + j) = r;
        }
    }
}

// ang[N,14] = relu(act) @ w_ang + b_ang ; one warp per row
__global__ __launch_bounds__(256) void ang_kernel(
    const float* __restrict__ act, const float* __restrict__ w_ang,
    const float* __restrict__ b_ang, float* __restrict__ angbuf)
{
    const int gw = (int)((blockIdx.x * blockDim.x + threadIdx.x) >> 5);
    const int lane = threadIdx.x & 31;
    if (gw >= NROWS) return;
    const float* row = act + (size_t)gw * DIM;
    float acc[14] = {};
    for (int i = lane; i < DIM; i += 32) {
        float a = fmaxf(row[i], 0.f);
        const float* w = w_ang + i * 14;
        #pragma unroll
        for (int j = 0; j < 14; j++) acc[j] = fmaf(a, w[j], acc[j]);
    }
    #pragma unroll
    for (int j = 0; j < 14; j++) {
        #pragma unroll
        for (int off = 16; off; off >>= 1)
            acc[j] += __shfl_down_sync(0xffffffffu, acc[j], off);
    }
    if (lane == 0) {
        float* o = angbuf + (size_t)gw * 14;
        #pragma unroll
        for (int j = 0; j < 14; j++) o[j] = acc[j] + b_ang[j];
    }
}

// Per-residue geometry: normalize angles, build/chain frames, place atoms.
__global__ __launch_bounds__(128) void epilogue_kernel(
    const float* __restrict__ angbuf,
    const float* __restrict__ rigids, const float* __restrict__ def_frames,
    const float* __restrict__ lit_pos, const float* __restrict__ atom_mask,
    const int* __restrict__ aatype, const int* __restrict__ gidx,
    float* __restrict__ out_angles, float* __restrict__ out_pred,
    float* __restrict__ out_frames)
{
    const int n = blockIdx.x * blockDim.x + threadIdx.x;
    if (n >= NROWS) return;
    const int aa = aatype[n];

    float s[8], c[8];
    s[0] = 0.f; c[0] = 1.f;
    #pragma unroll
    for (int i = 0; i < 7; i++) {
        float ss = angbuf[(size_t)n * 14 + 2 * i];
        float cc = angbuf[(size_t)n * 14 + 2 * i + 1];
        float inv = rsqrtf(fmaxf(ss * ss + cc * cc, 1e-12f));
        ss *= inv; cc *= inv;
        s[i + 1] = ss; c[i + 1] = cc;
        out_angles[(size_t)n * 14 + 2 * i] = ss;
        out_angles[(size_t)n * 14 + 2 * i + 1] = cc;
    }

    // frames_k = default_frames[aa,k] @ rotx(angle_k)   (3x4 repr: R|t)
    float FR[8][9], FT[8][3];
    #pragma unroll
    for (int k = 0; k < 8; k++) {
        const float* D = def_frames + ((size_t)aa * 8 + k) * 16;
        #pragma unroll
        for (int r = 0; r < 3; r++) {
            float d1 = D[r * 4 + 1], d2 = D[r * 4 + 2];
            FR[k][r * 3 + 0] = D[r * 4 + 0];
            FR[k][r * 3 + 1] = c[k] * d1 + s[k] * d2;
            FR[k][r * 3 + 2] = -s[k] * d1 + c[k] * d2;
            FT[k][r] = D[r * 4 + 3];
        }
    }

    // chi2..chi4 chained off previous chi frame
    #pragma unroll
    for (int k = 5; k <= 7; k++) {
        float R[9], T[3];
        #pragma unroll
        for (int r = 0; r < 3; r++) {
            #pragma unroll
            for (int cc2 = 0; cc2 < 3; cc2++)
                R[r * 3 + cc2] = FR[k - 1][r * 3 + 0] * FR[k][0 + cc2]
                               + FR[k - 1][r * 3 + 1] * FR[k][3 + cc2]
                               + FR[k - 1][r * 3 + 2] * FR[k][6 + cc2];
            T[r] = FR[k - 1][r * 3 + 0] * FT[k][0]
                 + FR[k - 1][r * 3 + 1] * FT[k][1]
                 + FR[k - 1][r * 3 + 2] * FT[k][2] + FT[k - 1][r];
        }
        #pragma unroll
        for (int q = 0; q < 9; q++) FR[k][q] = R[q];
        FT[k][0] = T[0]; FT[k][1] = T[1]; FT[k][2] = T[2];
    }

    // global = rigid ∘ frame
    const float* rg = rigids + (size_t)n * 16;
    float R0[9] = {rg[0], rg[1], rg[2], rg[4], rg[5], rg[6], rg[8], rg[9], rg[10]};
    float t0[3] = {rg[3], rg[7], rg[11]};

    #pragma unroll
    for (int k = 0; k < 8; k++) {
        float R[9], T[3];
        #pragma unroll
        for (int r = 0; r < 3; r++) {
            #pragma unroll
            for (int cc2 = 0; cc2 < 3; cc2++)
                R[r * 3 + cc2] = R0[r * 3 + 0] * FR[k][0 + cc2]
                               + R0[r * 3 + 1] * FR[k][3 + cc2]
                               + R0[r * 3 + 2] * FR[k][6 + cc2];
            T[r] = R0[r * 3 + 0] * FT[k][0] + R0[r * 3 + 1] * FT[k][1]
                 + R0[r * 3 + 2] * FT[k][2] + t0[r];
        }
        #pragma unroll
        for (int q = 0; q < 9; q++) FR[k][q] = R[q];
        FT[k][0] = T[0]; FT[k][1] = T[1]; FT[k][2] = T[2];

        float* of = out_frames + ((size_t)n * 8 + k) * 16;
        of[0]  = R[0]; of[1]  = R[1]; of[2]  = R[2]; of[3]  = T[0];
        of[4]  = R[3]; of[5]  = R[4]; of[6]  = R[5]; of[7]  = T[1];
        of[8]  = R[6]; of[9]  = R[7]; of[10] = R[8]; of[11] = T[2];
        of[12] = 0.f;  of[13] = 0.f;  of[14] = 0.f;  of[15] = 1.f;
    }

    // atom14 placement
    #pragma unroll
    for (int a = 0; a < 14; a++) {
        int g = gidx[aa * 14 + a];
        const float* p = lit_pos + ((size_t)aa * 14 + a) * 3;
        float m = atom_mask[aa * 14 + a];
        float px = p[0], py = p[1], pz = p[2];
        float* op = out_pred + ((size_t)n * 14 + a) * 3;
        op[0] = (FR[g][0] * px + FR[g][1] * py + FR[g][2] * pz + FT[g][0]) * m;
        op[1] = (FR[g][3] * px + FR[g][4] * py + FR[g][5] * pz + FT[g][1]) * m;
        op[2] = (FR[g][6] * px + FR[g][7] * py + FR[g][8] * pz + FT[g][2]) * m;
    }
}

extern "C" void kernel_launch(void* const* d_in, const int* in_sizes, int n_in,
                              void* d_out, int out_size)
{
    const float* rep0       = (const float*)d_in[0];
    const float* rep1       = (const float*)d_in[1];
    const float* w_in       = (const float*)d_in[2];
    const float* b_in       = (const float*)d_in[3];
    const float* w1         = (const float*)d_in[4];
    const float* b1         = (const float*)d_in[5];
    const float* w2         = (const float*)d_in[6];
    const float* b2         = (const float*)d_in[7];
    const float* w_ang      = (const float*)d_in[8];
    const float* b_ang      = (const float*)d_in[9];
    const float* rigids     = (const float*)d_in[10];
    const float* def_frames = (const float*)d_in[11];
    const float* lit_pos    = (const float*)d_in[12];
    const float* atom_mask  = (const float*)d_in[13];
    const int*   aatype     = (const int*)d_in[14];
    const int*   gidx       = (const int*)d_in[15];

    float *act, *h, *angb;
    cudaGetSymbolAddress((void**)&act, g_act);
    cudaGetSymbolAddress((void**)&h, g_h);
    cudaGetSymbolAddress((void**)&angb, g_ang);

    dim3 grid(DIM / BN, NROWS / BM);

    // act = (relu(rep0)+relu(rep1)) @ w_in + 2*b_in   (matmul linearity)
    gemm_relu<1, 0><<<grid, 256>>>(rep0, rep1, w_in, b_in, 2.f, act);
    // recycle 1
    gemm_relu<0, 0><<<grid, 256>>>(act, act, w1, b1, 1.f, h);
    gemm_relu<0, 1><<<grid, 256>>>(h, h, w2, b2, 1.f, act);
    // recycle 2
    gemm_relu<0, 0><<<grid, 256>>>(act, act, w1, b1, 1.f, h);
    gemm_relu<0, 1><<<grid, 256>>>(h, h, w2, b2, 1.f, act);
    // torsion head
    ang_kernel<<<NROWS / 8, 256>>>(act, w_ang, b_ang, angb);

    float* out = (float*)d_out;
    float* out_angles = out;                        // [N,7,2]
    float* out_pred   = out + (size_t)NROWS * 14;   // [N,14,3]
    float* out_frames = out + (size_t)NROWS * 56;   // [N,8,4,4]
    epilogue_kernel<<<(NROWS + 127) / 128, 128>>>(
        angb, rigids, def_frames, lit_pos, atom_mask, aatype, gidx,
        out_angles, out_pred, out_frames);
}

// round 3
// speedup vs baseline: 1.5542x; 1.5542x over previous
#include <cuda_runtime.h>
#include <cuda_bf16.h>
#include <math.h>
#include <stdint.h>

#define NROWS 32768
#define DIM 1024
#define NRES 21

// ---------------- scratch (no cudaMalloc allowed) ----------------
__device__ float g_act[(size_t)NROWS * DIM];
__device__ float g_h[(size_t)NROWS * DIM];
__device__ float g_ang[(size_t)NROWS * 14];
__device__ __nv_bfloat16 g_wt_hi[3][(size_t)DIM * DIM];  // transposed+split weights [n][k]
__device__ __nv_bfloat16 g_wt_lo[3][(size_t)DIM * DIM];

// ---------------- mma.sync helpers (baseline PTX, works at compute_103) ----------------
__device__ __forceinline__ uint32_t smem_to_u32(const void* p) {
    uint32_t a;
    asm("{ .reg .u64 t; cvta.to.shared.u64 t, %1; cvt.u32.u64 %0, t; }" : "=r"(a) : "l"(p));
    return a;
}
__device__ __forceinline__ void ldsm4(uint32_t (&r)[4], uint32_t addr) {
    asm volatile("ldmatrix.sync.aligned.m8n8.x4.shared.b16 {%0,%1,%2,%3}, [%4];"
                 : "=r"(r[0]), "=r"(r[1]), "=r"(r[2]), "=r"(r[3]) : "r"(addr));
}
__device__ __forceinline__ void mma_bf16(float* d, const uint32_t* a, const uint32_t* b) {
    asm volatile(
        "mma.sync.aligned.m16n8k16.row.col.f32.bf16.bf16.f32 "
        "{%0,%1,%2,%3}, {%4,%5,%6,%7}, {%8,%9}, {%0,%1,%2,%3};"
        : "+f"(d[0]), "+f"(d[1]), "+f"(d[2]), "+f"(d[3])
        : "r"(a[0]), "r"(a[1]), "r"(a[2]), "r"(a[3]), "r"(b[0]), "r"(b[1]));
}
__device__ __forceinline__ uint32_t pack_bf16(__nv_bfloat16 x, __nv_bfloat16 y) {
    __nv_bfloat162 t;
    t.x = x; t.y = y;
    return *(uint32_t*)&t;
}

// ---------------- tensor-core GEMM via mma.sync, bf16 split-2 ----------------
// C[M,N] = relu(A0)(+relu(A1)) @ W^T  where W given pre-split/transposed [n][k]
// tile 128x128, K-chunk 32, double buffered
#define KCHUNK 32
#define NITERS (DIM / KCHUNK)
#define PAD_K 40                       // bf16 elems per row (32 + 8 pad)
#define TILE_B (128 * PAD_K * 2)       // 10240 bytes
#define AH_OFF 0
#define AL_OFF TILE_B
#define BH_OFF (2 * TILE_B)
#define BL_OFF (3 * TILE_B)
#define STAGE_B (4 * TILE_B)           // 40960
#define SMEM_TOTAL (2 * STAGE_B)       // 81920

template<int DUAL, int RESID>
__global__ __launch_bounds__(256, 1) void gemm_mma(
    const float* __restrict__ A0, const float* __restrict__ A1,
    const __nv_bfloat16* __restrict__ Bhi, const __nv_bfloat16* __restrict__ Blo,
    const float* __restrict__ bias, float bias_scale, float* __restrict__ C)
{
    extern __shared__ char smem[];
    const uint32_t sb = smem_to_u32(smem);
    const int tid = threadIdx.x;
    const int wid = tid >> 5;
    const int lane = tid & 31;
    const int bx = blockIdx.x, by = blockIdx.y;
    const int wm = wid & 3;    // warp m index: rows wm*32
    const int wn = wid >> 2;   // warp n index: cols wn*64

    const int r = tid >> 1;        // producer row 0..127
    const int half = tid & 1;      // which 16-wide k half

    float d[2][8][4];
    #pragma unroll
    for (int i = 0; i < 2; i++)
        #pragma unroll
        for (int j = 0; j < 8; j++)
            #pragma unroll
            for (int q = 0; q < 4; q++) d[i][j][q] = 0.f;

    // producer staging regs
    float areg[16];
    uint4 bhreg0, bhreg1, blreg0, blreg1;

    auto loadG = [&](int kc) {
        const int kcol = kc * KCHUNK + half * 16;
        const float* p0 = A0 + (size_t)(by * 128 + r) * DIM + kcol;
        float4 v0 = ((const float4*)p0)[0];
        float4 v1 = ((const float4*)p0)[1];
        float4 v2 = ((const float4*)p0)[2];
        float4 v3 = ((const float4*)p0)[3];
        areg[0]=v0.x; areg[1]=v0.y; areg[2]=v0.z; areg[3]=v0.w;
        areg[4]=v1.x; areg[5]=v1.y; areg[6]=v1.z; areg[7]=v1.w;
        areg[8]=v2.x; areg[9]=v2.y; areg[10]=v2.z; areg[11]=v2.w;
        areg[12]=v3.x; areg[13]=v3.y; areg[14]=v3.z; areg[15]=v3.w;
        #pragma unroll
        for (int j = 0; j < 16; j++) areg[j] = fmaxf(areg[j], 0.f);
        if (DUAL) {
            const float* p1 = A1 + (size_t)(by * 128 + r) * DIM + kcol;
            float4 w0 = ((const float4*)p1)[0];
            float4 w1 = ((const float4*)p1)[1];
            float4 w2 = ((const float4*)p1)[2];
            float4 w3 = ((const float4*)p1)[3];
            float b[16] = {w0.x,w0.y,w0.z,w0.w, w1.x,w1.y,w1.z,w1.w,
                           w2.x,w2.y,w2.z,w2.w, w3.x,w3.y,w3.z,w3.w};
            #pragma unroll
            for (int j = 0; j < 16; j++) areg[j] += fmaxf(b[j], 0.f);
        }
        const __nv_bfloat16* ph = Bhi + (size_t)(bx * 128 + r) * DIM + kcol;
        const __nv_bfloat16* pl = Blo + (size_t)(bx * 128 + r) * DIM + kcol;
        bhreg0 = ((const uint4*)ph)[0]; bhreg1 = ((const uint4*)ph)[1];
        blreg0 = ((const uint4*)pl)[0]; blreg1 = ((const uint4*)pl)[1];
    };

    auto storeS = [&](int s) {
        uint32_t hi[8], lo[8];
        #pragma unroll
        for (int j = 0; j < 8; j++) {
            float x = areg[2*j], y = areg[2*j+1];
            __nv_bfloat16 hx = __float2bfloat16(x), hy = __float2bfloat16(y);
            float lx = x - __bfloat162float(hx);
            float ly = y - __bfloat162float(hy);
            hi[j] = pack_bf16(hx, hy);
            lo[j] = pack_bf16(__float2bfloat16(lx), __float2bfloat16(ly));
        }
        char* base = smem + s * STAGE_B;
        const int boff = r * (PAD_K * 2) + half * 32;
        *(uint4*)(base + AH_OFF + boff)      = make_uint4(hi[0], hi[1], hi[2], hi[3]);
        *(uint4*)(base + AH_OFF + boff + 16) = make_uint4(hi[4], hi[5], hi[6], hi[7]);
        *(uint4*)(base + AL_OFF + boff)      = make_uint4(lo[0], lo[1], lo[2], lo[3]);
        *(uint4*)(base + AL_OFF + boff + 16) = make_uint4(lo[4], lo[5], lo[6], lo[7]);
        *(uint4*)(base + BH_OFF + boff)      = bhreg0;
        *(uint4*)(base + BH_OFF + boff + 16) = bhreg1;
        *(uint4*)(base + BL_OFF + boff)      = blreg0;
        *(uint4*)(base + BL_OFF + boff + 16) = blreg1;
    };

    auto compute = [&](int s) {
        const uint32_t base = sb + s * STAGE_B;
        #pragma unroll
        for (int kh = 0; kh < 2; kh++) {
            const int k16 = kh * 16;
            // A fragments
            uint32_t ah[2][4], al[2][4];
            const uint32_t acol = (uint32_t)(k16 + ((lane >> 4) << 3));
            #pragma unroll
            for (int mt = 0; mt < 2; mt++) {
                const uint32_t arow = (uint32_t)(wm * 32 + mt * 16 + (lane & 15));
                const uint32_t aoff = arow * (PAD_K * 2) + acol * 2;
                ldsm4(ah[mt], base + AH_OFF + aoff);
                ldsm4(al[mt], base + AL_OFF + aoff);
            }
            const uint32_t bcol = (uint32_t)(k16 + (((lane >> 3) & 1) << 3));
            #pragma unroll
            for (int ntp = 0; ntp < 4; ntp++) {
                const uint32_t brow = (uint32_t)(wn * 64 + ntp * 16 + (lane & 7) +
                                                 (((lane >> 4) & 1) << 3));
                const uint32_t boff = brow * (PAD_K * 2) + bcol * 2;
                uint32_t bh[4], bl[4];
                ldsm4(bh, base + BH_OFF + boff);
                ldsm4(bl, base + BL_OFF + boff);
                #pragma unroll
                for (int mt = 0; mt < 2; mt++) {
                    #pragma unroll
                    for (int c = 0; c < 2; c++) {
                        float* dd = d[mt][ntp * 2 + c];
                        mma_bf16(dd, ah[mt], &bh[2 * c]);   // hh
                        mma_bf16(dd, ah[mt], &bl[2 * c]);   // hl
                        mma_bf16(dd, al[mt], &bh[2 * c]);   // lh
                    }
                }
            }
        }
    };

    // mainloop
    loadG(0); storeS(0);
    loadG(1);
    __syncthreads();
    for (int kc = 0; kc < NITERS; kc++) {
        if (kc + 1 < NITERS) storeS((kc + 1) & 1);
        if (kc + 2 < NITERS) loadG(kc + 2);
        compute(kc & 1);
        __syncthreads();
    }

    // epilogue: d-frag -> gmem with bias (+residual)
    const int rq = lane >> 2;       // 0..7
    const int cq = (lane & 3) * 2;  // 0,2,4,6
    #pragma unroll
    for (int mt = 0; mt < 2; mt++) {
        #pragma unroll
        for (int nt = 0; nt < 8; nt++) {
            const int col = bx * 128 + wn * 64 + nt * 8 + cq;
            const float b0 = bias_scale * bias[col];
            const float b1 = bias_scale * bias[col + 1];
            #pragma unroll
            for (int hrow = 0; hrow < 2; hrow++) {
                const int row = by * 128 + wm * 32 + mt * 16 + rq + hrow * 8;
                float* cp = C + (size_t)row * DIM + col;
                float2 v;
                v.x = d[mt][nt][hrow * 2 + 0] + b0;
                v.y = d[mt][nt][hrow * 2 + 1] + b1;
                if (RESID) {
                    float2 old = *(const float2*)cp;
                    v.x += old.x; v.y += old.y;
                }
                *(float2*)cp = v;
            }
        }
    }
}

// ---------------- weight transpose + bf16 split: Wt[n][k] = split(W[k][n]) ----------------
__global__ __launch_bounds__(256) void prep_w(const float* __restrict__ W,
                                              __nv_bfloat16* __restrict__ Whi,
                                              __nv_bfloat16* __restrict__ Wlo)
{
    __shared__ float t[32][33];
    const int n0 = blockIdx.x * 32, k0 = blockIdx.y * 32;
    const int tx = threadIdx.x, ty = threadIdx.y;  // (32, 8)
    #pragma unroll
    for (int i = 0; i < 4; i++)
        t[ty + i * 8][tx] = W[(size_t)(k0 + ty + i * 8) * DIM + n0 + tx];
    __syncthreads();
    #pragma unroll
    for (int i = 0; i < 4; i++) {
        float v = t[tx][ty + i * 8];
        __nv_bfloat16 hi = __float2bfloat16(v);
        float lo = v - __bfloat162float(hi);
        size_t o = (size_t)(n0 + ty + i * 8) * DIM + k0 + tx;
        Whi[o] = hi;
        Wlo[o] = __float2bfloat16(lo);
    }
}

// ---------------- torsion head ----------------
__global__ __launch_bounds__(256) void ang_kernel(
    const float* __restrict__ act, const float* __restrict__ w_ang,
    const float* __restrict__ b_ang, float* __restrict__ angbuf)
{
    const int gw = (int)((blockIdx.x * blockDim.x + threadIdx.x) >> 5);
    const int lane = threadIdx.x & 31;
    if (gw >= NROWS) return;
    const float* row = act + (size_t)gw * DIM;
    float acc[14] = {};
    for (int i = lane; i < DIM; i += 32) {
        float a = fmaxf(row[i], 0.f);
        const float* w = w_ang + i * 14;
        #pragma unroll
        for (int j = 0; j < 14; j++) acc[j] = fmaf(a, w[j], acc[j]);
    }
    #pragma unroll
    for (int j = 0; j < 14; j++) {
        #pragma unroll
        for (int off = 16; off; off >>= 1)
            acc[j] += __shfl_down_sync(0xffffffffu, acc[j], off);
    }
    if (lane == 0) {
        float* o = angbuf + (size_t)gw * 14;
        #pragma unroll
        for (int j = 0; j < 14; j++) o[j] = acc[j] + b_ang[j];
    }
}

// ---------------- per-residue geometry ----------------
__global__ __launch_bounds__(128) void epilogue_kernel(
    const float* __restrict__ angbuf,
    const float* __restrict__ rigids, const float* __restrict__ def_frames,
    const float* __restrict__ lit_pos, const float* __restrict__ atom_mask,
    const int* __restrict__ aatype, const int* __restrict__ gidx,
    float* __restrict__ out_angles, float* __restrict__ out_pred,
    float* __restrict__ out_frames)
{
    const int n = blockIdx.x * blockDim.x + threadIdx.x;
    if (n >= NROWS) return;
    const int aa = aatype[n];

    float s[8], c[8];
    s[0] = 0.f; c[0] = 1.f;
    #pragma unroll
    for (int i = 0; i < 7; i++) {
        float ss = angbuf[(size_t)n * 14 + 2 * i];
        float cc = angbuf[(size_t)n * 14 + 2 * i + 1];
        float inv = rsqrtf(fmaxf(ss * ss + cc * cc, 1e-12f));
        ss *= inv; cc *= inv;
        s[i + 1] = ss; c[i + 1] = cc;
        out_angles[(size_t)n * 14 + 2 * i] = ss;
        out_angles[(size_t)n * 14 + 2 * i + 1] = cc;
    }

    float FR[8][9], FT[8][3];
    #pragma unroll
    for (int k = 0; k < 8; k++) {
        const float* D = def_frames + ((size_t)aa * 8 + k) * 16;
        #pragma unroll
        for (int r = 0; r < 3; r++) {
            float d1 = D[r * 4 + 1], d2 = D[r * 4 + 2];
            FR[k][r * 3 + 0] = D[r * 4 + 0];
            FR[k][r * 3 + 1] = c[k] * d1 + s[k] * d2;
            FR[k][r * 3 + 2] = -s[k] * d1 + c[k] * d2;
            FT[k][r] = D[r * 4 + 3];
        }
    }

    #pragma unroll
    for (int k = 5; k <= 7; k++) {
        float R[9], T[3];
        #pragma unroll
        for (int r = 0; r < 3; r++) {
            #pragma unroll
            for (int cc2 = 0; cc2 < 3; cc2++)
                R[r * 3 + cc2] = FR[k - 1][r * 3 + 0] * FR[k][0 + cc2]
                               + FR[k - 1][r * 3 + 1] * FR[k][3 + cc2]
                               + FR[k - 1][r * 3 + 2] * FR[k][6 + cc2];
            T[r] = FR[k - 1][r * 3 + 0] * FT[k][0]
                 + FR[k - 1][r * 3 + 1] * FT[k][1]
                 + FR[k - 1][r * 3 + 2] * FT[k][2] + FT[k - 1][r];
        }
        #pragma unroll
        for (int q = 0; q < 9; q++) FR[k][q] = R[q];
        FT[k][0] = T[0]; FT[k][1] = T[1]; FT[k][2] = T[2];
    }

    const float* rg = rigids + (size_t)n * 16;
    float R0[9] = {rg[0], rg[1], rg[2], rg[4], rg[5], rg[6], rg[8], rg[9], rg[10]};
    float t0[3] = {rg[3], rg[7], rg[11]};

    #pragma unroll
    for (int k = 0; k < 8; k++) {
        float R[9], T[3];
        #pragma unroll
        for (int r = 0; r < 3; r++) {
            #pragma unroll
            for (int cc2 = 0; cc2 < 3; cc2++)
                R[r * 3 + cc2] = R0[r * 3 + 0] * FR[k][0 + cc2]
                               + R0[r * 3 + 1] * FR[k][3 + cc2]
                               + R0[r * 3 + 2] * FR[k][6 + cc2];
            T[r] = R0[r * 3 + 0] * FT[k][0] + R0[r * 3 + 1] * FT[k][1]
                 + R0[r * 3 + 2] * FT[k][2] + t0[r];
        }
        #pragma unroll
        for (int q = 0; q < 9; q++) FR[k][q] = R[q];
        FT[k][0] = T[0]; FT[k][1] = T[1]; FT[k][2] = T[2];

        float* of = out_frames + ((size_t)n * 8 + k) * 16;
        of[0]  = R[0]; of[1]  = R[1]; of[2]  = R[2]; of[3]  = T[0];
        of[4]  = R[3]; of[5]  = R[4]; of[6]  = R[5]; of[7]  = T[1];
        of[8]  = R[6]; of[9]  = R[7]; of[10] = R[8]; of[11] = T[2];
        of[12] = 0.f;  of[13] = 0.f;  of[14] = 0.f;  of[15] = 1.f;
    }

    #pragma unroll
    for (int a = 0; a < 14; a++) {
        int g = gidx[aa * 14 + a];
        const float* p = lit_pos + ((size_t)aa * 14 + a) * 3;
        float m = atom_mask[aa * 14 + a];
        float px = p[0], py = p[1], pz = p[2];
        float* op = out_pred + ((size_t)n * 14 + a) * 3;
        op[0] = (FR[g][0] * px + FR[g][1] * py + FR[g][2] * pz + FT[g][0]) * m;
        op[1] = (FR[g][3] * px + FR[g][4] * py + FR[g][5] * pz + FT[g][1]) * m;
        op[2] = (FR[g][6] * px + FR[g][7] * py + FR[g][8] * pz + FT[g][2]) * m;
    }
}

// ---------------- launch ----------------
extern "C" void kernel_launch(void* const* d_in, const int* in_sizes, int n_in,
                              void* d_out, int out_size)
{
    const float* rep0       = (const float*)d_in[0];
    const float* rep1       = (const float*)d_in[1];
    const float* w_in       = (const float*)d_in[2];
    const float* b_in       = (const float*)d_in[3];
    const float* w1         = (const float*)d_in[4];
    const float* b1         = (const float*)d_in[5];
    const float* w2         = (const float*)d_in[6];
    const float* b2         = (const float*)d_in[7];
    const float* w_ang      = (const float*)d_in[8];
    const float* b_ang      = (const float*)d_in[9];
    const float* rigids     = (const float*)d_in[10];
    const float* def_frames = (const float*)d_in[11];
    const float* lit_pos    = (const float*)d_in[12];
    const float* atom_mask  = (const float*)d_in[13];
    const int*   aatype     = (const int*)d_in[14];
    const int*   gidx       = (const int*)d_in[15];

    float *act, *h, *angb;
    __nv_bfloat16 *wth, *wtl;
    cudaGetSymbolAddress((void**)&act, g_act);
    cudaGetSymbolAddress((void**)&h, g_h);
    cudaGetSymbolAddress((void**)&angb, g_ang);
    cudaGetSymbolAddress((void**)&wth, g_wt_hi);
    cudaGetSymbolAddress((void**)&wtl, g_wt_lo);
    const size_t WSZ = (size_t)DIM * DIM;

    cudaFuncSetAttribute(gemm_mma<1,0>, cudaFuncAttributeMaxDynamicSharedMemorySize, SMEM_TOTAL);
    cudaFuncSetAttribute(gemm_mma<0,0>, cudaFuncAttributeMaxDynamicSharedMemorySize, SMEM_TOTAL);
    cudaFuncSetAttribute(gemm_mma<0,1>, cudaFuncAttributeMaxDynamicSharedMemorySize, SMEM_TOTAL);

    dim3 pg(DIM / 32, DIM / 32);
    dim3 pb(32, 8);
    prep_w<<<pg, pb>>>(w_in, wth + 0 * WSZ, wtl + 0 * WSZ);
    prep_w<<<pg, pb>>>(w1,   wth + 1 * WSZ, wtl + 1 * WSZ);
    prep_w<<<pg, pb>>>(w2,   wth + 2 * WSZ, wtl + 2 * WSZ);

    dim3 grid(DIM / 128, NROWS / 128);   // (8, 256)

    gemm_mma<1,0><<<grid, 256, SMEM_TOTAL>>>(rep0, rep1, wth + 0*WSZ, wtl + 0*WSZ, b_in, 2.f, act);
    gemm_mma<0,0><<<grid, 256, SMEM_TOTAL>>>(act, act, wth + 1*WSZ, wtl + 1*WSZ, b1, 1.f, h);
    gemm_mma<0,1><<<grid, 256, SMEM_TOTAL>>>(h, h,   wth + 2*WSZ, wtl + 2*WSZ, b2, 1.f, act);
    gemm_mma<0,0><<<grid, 256, SMEM_TOTAL>>>(act, act, wth + 1*WSZ, wtl + 1*WSZ, b1, 1.f, h);
    gemm_mma<0,1><<<grid, 256, SMEM_TOTAL>>>(h, h,   wth + 2*WSZ, wtl + 2*WSZ, b2, 1.f, act);

    ang_kernel<<<NROWS / 8, 256>>>(act, w_ang, b_ang, angb);

    float* out = (float*)d_out;
    float* out_angles = out;
    float* out_pred   = out + (size_t)NROWS * 14;
    float* out_frames = out + (size_t)NROWS * 56;
    epilogue_kernel<<<(NROWS + 127) / 128, 128>>>(
        angb, rigids, def_frames, lit_pos, atom_mask, aatype, gidx,
        out_angles, out_pred, out_frames);
}

// round 4
// speedup vs baseline: 2.8414x; 1.8282x over previous
#include <cuda_runtime.h>
#include <cuda_bf16.h>
#include <math.h>
#include <stdint.h>

#define NROWS 32768
#define DIM 1024
#define NRES 21

// ---------------- scratch (no cudaMalloc allowed) ----------------
__device__ float g_act[(size_t)NROWS * DIM];
__device__ float g_ang[(size_t)NROWS * 14];
__device__ __nv_bfloat16 g_wt_hi[3][(size_t)DIM * DIM];  // transposed weights [n][k]
__device__ __nv_bfloat16 g_wt_lo[3][(size_t)DIM * DIM];
__device__ __nv_bfloat16 g_sa_hi[(size_t)NROWS * DIM];   // activation split ping
__device__ __nv_bfloat16 g_sa_lo[(size_t)NROWS * DIM];
__device__ __nv_bfloat16 g_sb_hi[(size_t)NROWS * DIM];   // activation split pong
__device__ __nv_bfloat16 g_sb_lo[(size_t)NROWS * DIM];

// ---------------- PTX helpers (baseline compute_103 safe) ----------------
__device__ __forceinline__ uint32_t smem_to_u32(const void* p) {
    uint32_t a;
    asm("{ .reg .u64 t; cvta.to.shared.u64 t, %1; cvt.u32.u64 %0, t; }" : "=r"(a) : "l"(p));
    return a;
}
__device__ __forceinline__ void ldsm4(uint32_t (&r)[4], uint32_t addr) {
    asm volatile("ldmatrix.sync.aligned.m8n8.x4.shared.b16 {%0,%1,%2,%3}, [%4];"
                 : "=r"(r[0]), "=r"(r[1]), "=r"(r[2]), "=r"(r[3]) : "r"(addr));
}
__device__ __forceinline__ void mma_bf16(float* d, const uint32_t* a, const uint32_t* b) {
    asm volatile(
        "mma.sync.aligned.m16n8k16.row.col.f32.bf16.bf16.f32 "
        "{%0,%1,%2,%3}, {%4,%5,%6,%7}, {%8,%9}, {%0,%1,%2,%3};"
        : "+f"(d[0]), "+f"(d[1]), "+f"(d[2]), "+f"(d[3])
        : "r"(a[0]), "r"(a[1]), "r"(a[2]), "r"(a[3]), "r"(b[0]), "r"(b[1]));
}
__device__ __forceinline__ void cp16(uint32_t dst, const void* src) {
    asm volatile("cp.async.cg.shared.global [%0], [%1], 16;" :: "r"(dst), "l"(src));
}
__device__ __forceinline__ void cp_commit() {
    asm volatile("cp.async.commit_group;" ::: "memory");
}
template<int N>
__device__ __forceinline__ void cp_wait() {
    asm volatile("cp.async.wait_group %0;" :: "n"(N) : "memory");
}
__device__ __forceinline__ uint32_t pack_bf16(__nv_bfloat16 x, __nv_bfloat16 y) {
    __nv_bfloat162 t; t.x = x; t.y = y;
    return *(uint32_t*)&t;
}

// ---------------- GEMM: pre-split bf16 A and B, cp.async 3-stage ----------------
// smem tile: 128 rows x 128 bytes. cols(units of 16B): 0-3 = hi (32 bf16), 4-7 = lo.
// swizzle: unit' = unit ^ (row & 7)  -> conflict-free ldmatrix + cp.async.
#define KCHUNK 32
#define NITERS (DIM / KCHUNK)
#define TILE_S 16384            // 128 * 128B
#define STAGE_S (2 * TILE_S)    // A tile + B tile
#define NSTAGE 3
#define SMEM_TOTAL (NSTAGE * STAGE_S)   // 98304

// RESID: C += previous C;  WC: write fp32 C;  WSPLIT: write relu-split hi/lo
template<int RESID, int WC, int WSPLIT>
__global__ __launch_bounds__(256, 2) void gemm_mma(
    const __nv_bfloat16* __restrict__ Ahi, const __nv_bfloat16* __restrict__ Alo,
    const __nv_bfloat16* __restrict__ Bhi, const __nv_bfloat16* __restrict__ Blo,
    const float* __restrict__ bias, float bias_scale,
    float* __restrict__ C,
    __nv_bfloat16* __restrict__ Shi, __nv_bfloat16* __restrict__ Slo)
{
    extern __shared__ char smem[];
    const uint32_t sb = smem_to_u32(smem);
    const int tid = threadIdx.x;
    const int wid = tid >> 5;
    const int lane = tid & 31;
    const int bx = blockIdx.x, by = blockIdx.y;
    const int wm = wid & 3;    // warp rows: wm*32
    const int wn = wid >> 2;   // warp cols: wn*64

    float d[2][8][4];
    #pragma unroll
    for (int i = 0; i < 2; i++)
        #pragma unroll
        for (int j = 0; j < 8; j++)
            #pragma unroll
            for (int q = 0; q < 4; q++) d[i][j][q] = 0.f;

    // ---- producer: 2048 x 16B per stage, 8 per thread ----
    // i = tid + t*256 ; tile = i>>10 (0=A,1=B); idx = i&1023; row = idx>>3; unit = idx&7
    auto issue = [&](int kc) {
        const int s = kc % NSTAGE;
        const uint32_t stage = sb + s * STAGE_S;
        #pragma unroll
        for (int t = 0; t < 8; t++) {
            const int i = tid + t * 256;
            const int tile = i >> 10;
            const int idx = i & 1023;
            const int row = idx >> 3;
            const int unit = idx & 7;
            const __nv_bfloat16* plane;
            int grow;
            if (tile == 0) { plane = (unit < 4) ? Ahi : Alo; grow = by * 128 + row; }
            else           { plane = (unit < 4) ? Bhi : Blo; grow = bx * 128 + row; }
            const char* src = (const char*)plane + (size_t)grow * (DIM * 2)
                              + kc * 64 + (unit & 3) * 16;
            const uint32_t dst = stage + tile * TILE_S + row * 128
                                 + ((unit ^ (row & 7)) << 4);
            cp16(dst, src);
        }
        cp_commit();
    };

    issue(0);
    issue(1);

    const uint32_t abase0 = sb;            // + stage offset added per iter
    for (int kc = 0; kc < NITERS; kc++) {
        cp_wait<1>();
        __syncthreads();
        if (kc + 2 < NITERS) issue(kc + 2);

        const uint32_t stage = abase0 + (kc % NSTAGE) * STAGE_S;
        #pragma unroll
        for (int kh = 0; kh < 2; kh++) {
            // A fragments (hi & lo)
            uint32_t ah[2][4], al[2][4];
            const int aunit = kh * 2 + (lane >> 4);
            #pragma unroll
            for (int mt = 0; mt < 2; mt++) {
                const int arow = wm * 32 + mt * 16 + (lane & 15);
                const uint32_t hiaddr = stage + arow * 128 + (((aunit) ^ (arow & 7)) << 4);
                ldsm4(ah[mt], hiaddr);
                ldsm4(al[mt], hiaddr ^ 64);   // unit+4 flips bit2 of unit -> xor 64
            }
            const int bunit = kh * 2 + ((lane >> 3) & 1);
            #pragma unroll
            for (int ntp = 0; ntp < 4; ntp++) {
                const int brow = wn * 64 + ntp * 16 + (lane & 7) + (((lane >> 4) & 1) << 3);
                const uint32_t hiaddr = stage + TILE_S + brow * 128
                                        + (((bunit) ^ (brow & 7)) << 4);
                uint32_t bh[4], bl[4];
                ldsm4(bh, hiaddr);
                ldsm4(bl, hiaddr ^ 64);
                #pragma unroll
                for (int mt = 0; mt < 2; mt++) {
                    #pragma unroll
                    for (int c = 0; c < 2; c++) {
                        float* dd = d[mt][ntp * 2 + c];
                        mma_bf16(dd, ah[mt], &bh[2 * c]);
                        mma_bf16(dd, ah[mt], &bl[2 * c]);
                        mma_bf16(dd, al[mt], &bh[2 * c]);
                    }
                }
            }
        }
    }

    // ---- epilogue ----
    const int rq = lane >> 2;
    const int cq = (lane & 3) * 2;
    #pragma unroll
    for (int mt = 0; mt < 2; mt++) {
        #pragma unroll
        for (int nt = 0; nt < 8; nt++) {
            const int col = bx * 128 + wn * 64 + nt * 8 + cq;
            const float b0 = bias_scale * bias[col];
            const float b1 = bias_scale * bias[col + 1];
            #pragma unroll
            for (int hrow = 0; hrow < 2; hrow++) {
                const int row = by * 128 + wm * 32 + mt * 16 + rq + hrow * 8;
                float vx = d[mt][nt][hrow * 2 + 0] + b0;
                float vy = d[mt][nt][hrow * 2 + 1] + b1;
                float* cp = C + (size_t)row * DIM + col;
                if (RESID) {
                    float2 old = *(const float2*)cp;
                    vx += old.x; vy += old.y;
                }
                if (WC) *(float2*)cp = make_float2(vx, vy);
                if (WSPLIT) {
                    float rx = fmaxf(vx, 0.f), ry = fmaxf(vy, 0.f);
                    __nv_bfloat16 hx = __float2bfloat16(rx);
                    __nv_bfloat16 hy = __float2bfloat16(ry);
                    float lx = rx - __bfloat162float(hx);
                    float ly = ry - __bfloat162float(hy);
                    const size_t o = (size_t)row * DIM + col;
                    *(uint32_t*)(Shi + o) = pack_bf16(hx, hy);
                    *(uint32_t*)(Slo + o) = pack_bf16(__float2bfloat16(lx),
                                                      __float2bfloat16(ly));
                }
            }
        }
    }
}

// ---------------- fuse0: split(relu(rep0)+relu(rep1)) -> bf16 hi/lo ----------------
__global__ __launch_bounds__(256) void fuse0(
    const float* __restrict__ rep0, const float* __restrict__ rep1,
    __nv_bfloat16* __restrict__ Shi, __nv_bfloat16* __restrict__ Slo)
{
    const size_t i = ((size_t)blockIdx.x * blockDim.x + threadIdx.x) * 4;
    float4 a = *(const float4*)(rep0 + i);
    float4 b = *(const float4*)(rep1 + i);
    float v[4] = {fmaxf(a.x, 0.f) + fmaxf(b.x, 0.f),
                  fmaxf(a.y, 0.f) + fmaxf(b.y, 0.f),
                  fmaxf(a.z, 0.f) + fmaxf(b.z, 0.f),
                  fmaxf(a.w, 0.f) + fmaxf(b.w, 0.f)};
    uint32_t hi[2], lo[2];
    #pragma unroll
    for (int q = 0; q < 2; q++) {
        __nv_bfloat16 hx = __float2bfloat16(v[2*q]);
        __nv_bfloat16 hy = __float2bfloat16(v[2*q+1]);
        float lx = v[2*q] - __bfloat162float(hx);
        float ly = v[2*q+1] - __bfloat162float(hy);
        hi[q] = pack_bf16(hx, hy);
        lo[q] = pack_bf16(__float2bfloat16(lx), __float2bfloat16(ly));
    }
    *(uint2*)(Shi + i) = make_uint2(hi[0], hi[1]);
    *(uint2*)(Slo + i) = make_uint2(lo[0], lo[1]);
}

// ---------------- weight transpose + bf16 split ----------------
__global__ __launch_bounds__(256) void prep_w(const float* __restrict__ W,
                                              __nv_bfloat16* __restrict__ Whi,
                                              __nv_bfloat16* __restrict__ Wlo)
{
    __shared__ float t[32][33];
    const int n0 = blockIdx.x * 32, k0 = blockIdx.y * 32;
    const int tx = threadIdx.x, ty = threadIdx.y;  // (32, 8)
    #pragma unroll
    for (int i = 0; i < 4; i++)
        t[ty + i * 8][tx] = W[(size_t)(k0 + ty + i * 8) * DIM + n0 + tx];
    __syncthreads();
    #pragma unroll
    for (int i = 0; i < 4; i++) {
        float v = t[tx][ty + i * 8];
        __nv_bfloat16 hi = __float2bfloat16(v);
        float lo = v - __bfloat162float(hi);
        size_t o = (size_t)(n0 + ty + i * 8) * DIM + k0 + tx;
        Whi[o] = hi;
        Wlo[o] = __float2bfloat16(lo);
    }
}

// ---------------- torsion head ----------------
__global__ __launch_bounds__(256) void ang_kernel(
    const float* __restrict__ act, const float* __restrict__ w_ang,
    const float* __restrict__ b_ang, float* __restrict__ angbuf)
{
    const int gw = (int)((blockIdx.x * blockDim.x + threadIdx.x) >> 5);
    const int lane = threadIdx.x & 31;
    if (gw >= NROWS) return;
    const float* row = act + (size_t)gw * DIM;
    float acc[14] = {};
    for (int i = lane; i < DIM; i += 32) {
        float a = fmaxf(row[i], 0.f);
        const float* w = w_ang + i * 14;
        #pragma unroll
        for (int j = 0; j < 14; j++) acc[j] = fmaf(a, w[j], acc[j]);
    }
    #pragma unroll
    for (int j = 0; j < 14; j++) {
        #pragma unroll
        for (int off = 16; off; off >>= 1)
            acc[j] += __shfl_down_sync(0xffffffffu, acc[j], off);
    }
    if (lane == 0) {
        float* o = angbuf + (size_t)gw * 14;
        #pragma unroll
        for (int j = 0; j < 14; j++) o[j] = acc[j] + b_ang[j];
    }
}

// ---------------- per-residue geometry ----------------
__global__ __launch_bounds__(128) void epilogue_kernel(
    const float* __restrict__ angbuf,
    const float* __restrict__ rigids, const float* __restrict__ def_frames,
    const float* __restrict__ lit_pos, const float* __restrict__ atom_mask,
    const int* __restrict__ aatype, const int* __restrict__ gidx,
    float* __restrict__ out_angles, float* __restrict__ out_pred,
    float* __restrict__ out_frames)
{
    const int n = blockIdx.x * blockDim.x + threadIdx.x;
    if (n >= NROWS) return;
    const int aa = aatype[n];

    float s[8], c[8];
    s[0] = 0.f; c[0] = 1.f;
    #pragma unroll
    for (int i = 0; i < 7; i++) {
        float ss = angbuf[(size_t)n * 14 + 2 * i];
        float cc = angbuf[(size_t)n * 14 + 2 * i + 1];
        float inv = rsqrtf(fmaxf(ss * ss + cc * cc, 1e-12f));
        ss *= inv; cc *= inv;
        s[i + 1] = ss; c[i + 1] = cc;
        out_angles[(size_t)n * 14 + 2 * i] = ss;
        out_angles[(size_t)n * 14 + 2 * i + 1] = cc;
    }

    float FR[8][9], FT[8][3];
    #pragma unroll
    for (int k = 0; k < 8; k++) {
        const float* D = def_frames + ((size_t)aa * 8 + k) * 16;
        #pragma unroll
        for (int r = 0; r < 3; r++) {
            float d1 = D[r * 4 + 1], d2 = D[r * 4 + 2];
            FR[k][r * 3 + 0] = D[r * 4 + 0];
            FR[k][r * 3 + 1] = c[k] * d1 + s[k] * d2;
            FR[k][r * 3 + 2] = -s[k] * d1 + c[k] * d2;
            FT[k][r] = D[r * 4 + 3];
        }
    }

    #pragma unroll
    for (int k = 5; k <= 7; k++) {
        float R[9], T[3];
        #pragma unroll
        for (int r = 0; r < 3; r++) {
            #pragma unroll
            for (int cc2 = 0; cc2 < 3; cc2++)
                R[r * 3 + cc2] = FR[k - 1][r * 3 + 0] * FR[k][0 + cc2]
                               + FR[k - 1][r * 3 + 1] * FR[k][3 + cc2]
                               + FR[k - 1][r * 3 + 2] * FR[k][6 + cc2];
            T[r] = FR[k - 1][r * 3 + 0] * FT[k][0]
                 + FR[k - 1][r * 3 + 1] * FT[k][1]
                 + FR[k - 1][r * 3 + 2] * FT[k][2] + FT[k - 1][r];
        }
        #pragma unroll
        for (int q = 0; q < 9; q++) FR[k][q] = R[q];
        FT[k][0] = T[0]; FT[k][1] = T[1]; FT[k][2] = T[2];
    }

    const float* rg = rigids + (size_t)n * 16;
    float R0[9] = {rg[0], rg[1], rg[2], rg[4], rg[5], rg[6], rg[8], rg[9], rg[10]};
    float t0[3] = {rg[3], rg[7], rg[11]};

    #pragma unroll
    for (int k = 0; k < 8; k++) {
        float R[9], T[3];
        #pragma unroll
        for (int r = 0; r < 3; r++) {
            #pragma unroll
            for (int cc2 = 0; cc2 < 3; cc2++)
                R[r * 3 + cc2] = R0[r * 3 + 0] * FR[k][0 + cc2]
                               + R0[r * 3 + 1] * FR[k][3 + cc2]
                               + R0[r * 3 + 2] * FR[k][6 + cc2];
            T[r] = R0[r * 3 + 0] * FT[k][0] + R0[r * 3 + 1] * FT[k][1]
                 + R0[r * 3 + 2] * FT[k][2] + t0[r];
        }
        #pragma unroll
        for (int q = 0; q < 9; q++) FR[k][q] = R[q];
        FT[k][0] = T[0]; FT[k][1] = T[1]; FT[k][2] = T[2];

        float* of = out_frames + ((size_t)n * 8 + k) * 16;
        of[0]  = R[0]; of[1]  = R[1]; of[2]  = R[2]; of[3]  = T[0];
        of[4]  = R[3]; of[5]  = R[4]; of[6]  = R[5]; of[7]  = T[1];
        of[8]  = R[6]; of[9]  = R[7]; of[10] = R[8]; of[11] = T[2];
        of[12] = 0.f;  of[13] = 0.f;  of[14] = 0.f;  of[15] = 1.f;
    }

    #pragma unroll
    for (int a = 0; a < 14; a++) {
        int g = gidx[aa * 14 + a];
        const float* p = lit_pos + ((size_t)aa * 14 + a) * 3;
        float m = atom_mask[aa * 14 + a];
        float px = p[0], py = p[1], pz = p[2];
        float* op = out_pred + ((size_t)n * 14 + a) * 3;
        op[0] = (FR[g][0] * px + FR[g][1] * py + FR[g][2] * pz + FT[g][0]) * m;
        op[1] = (FR[g][3] * px + FR[g][4] * py + FR[g][5] * pz + FT[g][1]) * m;
        op[2] = (FR[g][6] * px + FR[g][7] * py + FR[g][8] * pz + FT[g][2]) * m;
    }
}

// ---------------- launch ----------------
extern "C" void kernel_launch(void* const* d_in, const int* in_sizes, int n_in,
                              void* d_out, int out_size)
{
    const float* rep0       = (const float*)d_in[0];
    const float* rep1       = (const float*)d_in[1];
    const float* w_in       = (const float*)d_in[2];
    const float* b_in       = (const float*)d_in[3];
    const float* w1         = (const float*)d_in[4];
    const float* b1         = (const float*)d_in[5];
    const float* w2         = (const float*)d_in[6];
    const float* b2         = (const float*)d_in[7];
    const float* w_ang      = (const float*)d_in[8];
    const float* b_ang      = (const float*)d_in[9];
    const float* rigids     = (const float*)d_in[10];
    const float* def_frames = (const float*)d_in[11];
    const float* lit_pos    = (const float*)d_in[12];
    const float* atom_mask  = (const float*)d_in[13];
    const int*   aatype     = (const int*)d_in[14];
    const int*   gidx       = (const int*)d_in[15];

    float *act, *angb;
    __nv_bfloat16 *wth, *wtl, *sah, *sal, *sbh, *sbl;
    cudaGetSymbolAddress((void**)&act, g_act);
    cudaGetSymbolAddress((void**)&angb, g_ang);
    cudaGetSymbolAddress((void**)&wth, g_wt_hi);
    cudaGetSymbolAddress((void**)&wtl, g_wt_lo);
    cudaGetSymbolAddress((void**)&sah, g_sa_hi);
    cudaGetSymbolAddress((void**)&sal, g_sa_lo);
    cudaGetSymbolAddress((void**)&sbh, g_sb_hi);
    cudaGetSymbolAddress((void**)&sbl, g_sb_lo);
    const size_t WSZ = (size_t)DIM * DIM;

    cudaFuncSetAttribute(gemm_mma<0,1,1>, cudaFuncAttributeMaxDynamicSharedMemorySize, SMEM_TOTAL);
    cudaFuncSetAttribute(gemm_mma<0,0,1>, cudaFuncAttributeMaxDynamicSharedMemorySize, SMEM_TOTAL);
    cudaFuncSetAttribute(gemm_mma<1,1,1>, cudaFuncAttributeMaxDynamicSharedMemorySize, SMEM_TOTAL);
    cudaFuncSetAttribute(gemm_mma<1,1,0>, cudaFuncAttributeMaxDynamicSharedMemorySize, SMEM_TOTAL);

    dim3 pg(DIM / 32, DIM / 32), pb(32, 8);
    prep_w<<<pg, pb>>>(w_in, wth + 0 * WSZ, wtl + 0 * WSZ);
    prep_w<<<pg, pb>>>(w1,   wth + 1 * WSZ, wtl + 1 * WSZ);
    prep_w<<<pg, pb>>>(w2,   wth + 2 * WSZ, wtl + 2 * WSZ);

    fuse0<<<(NROWS * DIM) / (256 * 4), 256>>>(rep0, rep1, sah, sal);

    dim3 grid(DIM / 128, NROWS / 128);  // (8, 256)

    // G1: act = split_in @ w_in^T + 2*b_in ; write act + split(relu(act)) -> sb
    gemm_mma<0,1,1><<<grid, 256, SMEM_TOTAL>>>(sah, sal, wth + 0*WSZ, wtl + 0*WSZ,
                                               b_in, 2.f, act, sbh, sbl);
    // G2: h-split = split(relu(sb @ w1^T + b1)) -> sa  (no fp32 h!)
    gemm_mma<0,0,1><<<grid, 256, SMEM_TOTAL>>>(sbh, sbl, wth + 1*WSZ, wtl + 1*WSZ,
                                               b1, 1.f, act /*unused*/, sah, sal);
    // G3: act += sa @ w2^T + b2 ; write act + split(relu(act)) -> sb
    gemm_mma<1,1,1><<<grid, 256, SMEM_TOTAL>>>(sah, sal, wth + 2*WSZ, wtl + 2*WSZ,
                                               b2, 1.f, act, sbh, sbl);
    // G4
    gemm_mma<0,0,1><<<grid, 256, SMEM_TOTAL>>>(sbh, sbl, wth + 1*WSZ, wtl + 1*WSZ,
                                               b1, 1.f, act /*unused*/, sah, sal);
    // G5: act += sa @ w2^T + b2 (no split needed)
    gemm_mma<1,1,0><<<grid, 256, SMEM_TOTAL>>>(sah, sal, wth + 2*WSZ, wtl + 2*WSZ,
                                               b2, 1.f, act, sbh, sbl);

    ang_kernel<<<NROWS / 8, 256>>>(act, w_ang, b_ang, angb);

    float* out = (float*)d_out;
    float* out_angles = out;
    float* out_pred   = out + (size_t)NROWS * 14;
    float* out_frames = out + (size_t)NROWS * 56;
    epilogue_kernel<<<(NROWS + 127) / 128, 128>>>(
        angb, rigids, def_frames, lit_pos, atom_mask, aatype, gidx,
        out_angles, out_pred, out_frames);
}